// round 17
// baseline (speedup 1.0000x reference)
#include <cuda_runtime.h>
#include <cuda_bf16.h>
#include <cstdint>

// Problem constants
#define BATCH 2
#define SEQ   2048
#define DMODEL 1024
#define DSTATE 16
#define LC 32            // chunk length
#define NC (SEQ / LC)    // 64 chunks
#define CG 4             // chunk groups in k3
#define NCG (NC / CG)    // 16 chunks per group

typedef unsigned long long ull;

// Scratch (device globals; 16B aligned for vector loads)
__device__ __align__(16) float g_bt[BATCH * SEQ * DSTATE];              // (b,l,s)
__device__ __align__(16) float g_hstate[BATCH * NC * DMODEL * DSTATE];  // chunk-end states
__device__ __align__(16) float g_hentry[BATCH * NC * DMODEL * DSTATE];  // chunk-entry states
__device__ __align__(16) float g_abar[DMODEL * DSTATE];                 // exp(-exp(logA))
__device__ __align__(16) float g_aL[DMODEL * DSTATE];                   // abar^LC

// ---- packed fp32x2 helpers ------------------------------------------------
__device__ __forceinline__ ull fma2(ull a, ull b, ull c) {
    ull d;
    asm("fma.rn.f32x2 %0, %1, %2, %3;" : "=l"(d) : "l"(a), "l"(b), "l"(c));
    return d;
}
__device__ __forceinline__ float2 unpack2(ull v) {
    float2 f;
    asm("mov.b64 {%0, %1}, %2;" : "=f"(f.x), "=f"(f.y) : "l"(v));
    return f;
}
// ---- cp.async helpers ------------------------------------------------------
__device__ __forceinline__ void cp_async16(unsigned int smem_addr, const void* gptr) {
    asm volatile("cp.async.cg.shared.global [%0], [%1], 16;" :: "r"(smem_addr), "l"(gptr));
}
__device__ __forceinline__ void cp_async_commit() {
    asm volatile("cp.async.commit_group;");
}
__device__ __forceinline__ void cp_async_wait0() {
    asm volatile("cp.async.wait_group 0;" ::: "memory");
}

// ---------------------------------------------------------------------------
// K1: B_t[b,l,s] = sum_d x[b,l,d] * B_w[s,d]   (one warp per FOUR rows).
// Bw is L1-resident; 4 rows per warp amortizes its re-reads (LSU-byte bound).
// Blocks >= K1_BLOCKS run the k0 precompute (abar, aL).
// ---------------------------------------------------------------------------
#define K1_BLOCKS ((BATCH * SEQ / 4) * 32 / 128)   // 256
#define K0_BLOCKS ((DMODEL * DSTATE) / 128)        // 128

__global__ void __launch_bounds__(128)
k1_bproj(const float* __restrict__ x, const float* __restrict__ Bw,
         const float* __restrict__ logA) {
    if (blockIdx.x >= K1_BLOCKS) {
        int i = (blockIdx.x - K1_BLOCKS) * 128 + threadIdx.x;
        float a = expf(-expf(logA[i]));
        g_abar[i] = a;
        float aL = a;                   // a^32 = 5 squarings
        aL = aL * aL; aL = aL * aL; aL = aL * aL; aL = aL * aL; aL = aL * aL;
        g_aL[i] = aL;
        return;
    }

    const int warp = (blockIdx.x * 128 + threadIdx.x) >> 5;  // 0..BATCH*SEQ/4-1
    const int lane = threadIdx.x & 31;
    const int r0 = warp * 4;

    const ulonglong2* xr0 = reinterpret_cast<const ulonglong2*>(x + (size_t)(r0 + 0) * DMODEL) + lane;
    const ulonglong2* xr1 = reinterpret_cast<const ulonglong2*>(x + (size_t)(r0 + 1) * DMODEL) + lane;
    const ulonglong2* xr2 = reinterpret_cast<const ulonglong2*>(x + (size_t)(r0 + 2) * DMODEL) + lane;
    const ulonglong2* xr3 = reinterpret_cast<const ulonglong2*>(x + (size_t)(r0 + 3) * DMODEL) + lane;

    ull acc0[DSTATE], acc1[DSTATE], acc2[DSTATE], acc3[DSTATE];
#pragma unroll
    for (int s = 0; s < DSTATE; s++) {
        acc0[s] = 0ull; acc1[s] = 0ull; acc2[s] = 0ull; acc3[s] = 0ull;
    }

#pragma unroll
    for (int it = 0; it < DMODEL / 128; it++) {
        ulonglong2 xa = xr0[it * 32];
        ulonglong2 xb = xr1[it * 32];
        ulonglong2 xc = xr2[it * 32];
        ulonglong2 xd = xr3[it * 32];
#pragma unroll
        for (int s = 0; s < DSTATE; s++) {
            ulonglong2 bv = reinterpret_cast<const ulonglong2*>(
                Bw + (size_t)s * DMODEL + it * 128)[lane];
            acc0[s] = fma2(xa.x, bv.x, acc0[s]);
            acc0[s] = fma2(xa.y, bv.y, acc0[s]);
            acc1[s] = fma2(xb.x, bv.x, acc1[s]);
            acc1[s] = fma2(xb.y, bv.y, acc1[s]);
            acc2[s] = fma2(xc.x, bv.x, acc2[s]);
            acc2[s] = fma2(xc.y, bv.y, acc2[s]);
            acc3[s] = fma2(xd.x, bv.x, acc3[s]);
            acc3[s] = fma2(xd.y, bv.y, acc3[s]);
        }
    }
#pragma unroll
    for (int s = 0; s < DSTATE; s++) {
        float2 p0 = unpack2(acc0[s]);
        float2 p1 = unpack2(acc1[s]);
        float2 p2 = unpack2(acc2[s]);
        float2 p3 = unpack2(acc3[s]);
        float v0 = p0.x + p0.y;
        float v1 = p1.x + p1.y;
        float v2 = p2.x + p2.y;
        float v3 = p3.x + p3.y;
#pragma unroll
        for (int m = 16; m >= 1; m >>= 1) {
            v0 += __shfl_xor_sync(0xffffffffu, v0, m);
            v1 += __shfl_xor_sync(0xffffffffu, v1, m);
            v2 += __shfl_xor_sync(0xffffffffu, v2, m);
            v3 += __shfl_xor_sync(0xffffffffu, v3, m);
        }
        if (lane == s) {
            g_bt[(r0 + 0) * DSTATE + s] = v0;
            g_bt[(r0 + 1) * DSTATE + s] = v1;
            g_bt[(r0 + 2) * DSTATE + s] = v2;
            g_bt[(r0 + 3) * DSTATE + s] = v3;
        }
    }
}

// ---------------------------------------------------------------------------
// K2: local chunk scan, state-split across thread pairs.
// grid=(NC, DMODEL/64, BATCH), block=128. Thread pair owns one d-channel;
// each thread scans 8 of 16 states and writes its half of the chunk-end state.
// ---------------------------------------------------------------------------
__global__ void __launch_bounds__(128)
k2_localscan() {
    const int c = blockIdx.x;
    const int dl = threadIdx.x >> 1;          // local d: 0..63
    const int sh = threadIdx.x & 1;           // state half
    const int d = blockIdx.y * 64 + dl;
    const int b = blockIdx.z;

    __shared__ ulonglong2 bts[LC][4];   // 16 floats = 4 ulonglong2 per step
    {
        unsigned int bt_addr = (unsigned int)__cvta_generic_to_shared(&bts[0][0]);
        const float* btg = g_bt + ((size_t)b * SEQ + (size_t)c * LC) * DSTATE;
        cp_async16(bt_addr + threadIdx.x * 16, btg + threadIdx.x * 4);
        cp_async_commit();
    }

    ull a2[4], h2[4];
    {
        const ulonglong2* ap = reinterpret_cast<const ulonglong2*>(
            g_abar + d * DSTATE) + sh * 2;
#pragma unroll
        for (int j = 0; j < 2; j++) {
            ulonglong2 av = ap[j];
            a2[2*j+0] = av.x; a2[2*j+1] = av.y;
        }
    }
#pragma unroll
    for (int k = 0; k < 4; k++) h2[k] = 0ull;

    cp_async_wait0();
    __syncthreads();

#pragma unroll
    for (int l = 0; l < LC; l++) {
#pragma unroll
        for (int j = 0; j < 2; j++) {
            ulonglong2 bv = bts[l][sh * 2 + j];
            h2[2*j+0] = fma2(a2[2*j+0], h2[2*j+0], bv.x);
            h2[2*j+1] = fma2(a2[2*j+1], h2[2*j+1], bv.y);
        }
    }

    ulonglong2* out = reinterpret_cast<ulonglong2*>(
        g_hstate + (((size_t)b * NC + c) * DMODEL + d) * DSTATE) + sh * 2;
#pragma unroll
    for (int j = 0; j < 2; j++)
        out[j] = make_ulonglong2(h2[2*j], h2[2*j+1]);
}

// ---------------------------------------------------------------------------
// K3: cross-chunk combine, 2-level. Block = 256 = 64 ds x 4 chunk-groups.
// ---------------------------------------------------------------------------
__global__ void k3_combine() {
    const int ds_local = threadIdx.x & 63;
    const int cg = threadIdx.x >> 6;          // 0..3
    const int ds = blockIdx.x * 64 + ds_local;
    const int b = blockIdx.y;

    const float aL = g_aL[ds];
    float aL16 = aL;                          // aL^NCG, NCG=16 -> 4 squarings
    aL16 = aL16 * aL16; aL16 = aL16 * aL16; aL16 = aL16 * aL16; aL16 = aL16 * aL16;

    const size_t stride = (size_t)DMODEL * DSTATE;
    const float* __restrict__ src =
        g_hstate + (size_t)b * NC * stride + (size_t)cg * NCG * stride + ds;
    float* __restrict__ dst =
        g_hentry + (size_t)b * NC * stride + (size_t)cg * NCG * stride + ds;

    float e[NCG];
#pragma unroll
    for (int k = 0; k < NCG; k++) e[k] = src[(size_t)k * stride];

    float G = 0.f;
#pragma unroll
    for (int k = 0; k < NCG; k++) G = fmaf(aL, G, e[k]);

    __shared__ float GE[CG][64];
    GE[cg][ds_local] = G;
    __syncthreads();

    float E = 0.f;
#pragma unroll
    for (int g = 0; g < CG - 1; g++)
        if (g < cg) E = fmaf(aL16, E, GE[g][ds_local]);

    float H = E;
#pragma unroll
    for (int k = 0; k < NCG; k++) {
        dst[(size_t)k * stride] = H;
        H = fmaf(aL, H, e[k]);
    }
}

// ---------------------------------------------------------------------------
// K4: final scan + output, state-split across thread pairs.
// grid=(NC, DMODEL/64, BATCH), block=128.
// ---------------------------------------------------------------------------
__global__ void __launch_bounds__(128)
k4_output(const float* __restrict__ x,
          const float* __restrict__ Cw,
          const float* __restrict__ Dv,
          float* __restrict__ y) {
    const int c = blockIdx.x;
    const int dl = threadIdx.x >> 1;          // local d: 0..63
    const int sh = threadIdx.x & 1;           // state half: 0 or 1
    const int d = blockIdx.y * 64 + dl;
    const int b = blockIdx.z;

    __shared__ float sx[LC * 64];             // x tile: 8KB
    __shared__ ulonglong2 bts[LC][4];         // B_t tile: 2KB

    const size_t base = ((size_t)b * SEQ + (size_t)c * LC) * DMODEL + blockIdx.y * 64;

    // async-stage x tile: 512 float4 = 4 per thread
    {
        unsigned int sx_addr = (unsigned int)__cvta_generic_to_shared(sx);
        const float* xg = x + base;
#pragma unroll
        for (int k = 0; k < 4; k++) {
            int i = threadIdx.x + 128 * k;    // float4 index 0..511
            int l = i >> 4;                   // 16 float4 per row
            int d4 = i & 15;
            cp_async16(sx_addr + i * 16, xg + (size_t)l * DMODEL + d4 * 4);
        }
    }
    // async-stage B_t tile: 128 float4 = 1 per thread
    {
        unsigned int bt_addr = (unsigned int)__cvta_generic_to_shared(&bts[0][0]);
        const float* btg = g_bt + ((size_t)b * SEQ + (size_t)c * LC) * DSTATE;
        cp_async16(bt_addr + threadIdx.x * 16, btg + threadIdx.x * 4);
    }
    cp_async_commit();

    // per-thread register loads: this thread's 8 states (half sh)
    ull a2[4], h2[4], cw2[4];
    {
        const ulonglong2* hin = reinterpret_cast<const ulonglong2*>(
            g_hentry + (((size_t)b * NC + c) * DMODEL + d) * DSTATE) + sh * 2;
        const ulonglong2* cwp = reinterpret_cast<const ulonglong2*>(
            Cw + (size_t)d * DSTATE) + sh * 2;
        const ulonglong2* ap = reinterpret_cast<const ulonglong2*>(
            g_abar + d * DSTATE) + sh * 2;
#pragma unroll
        for (int j = 0; j < 2; j++) {
            ulonglong2 hv = hin[j];  h2[2*j] = hv.x;  h2[2*j+1] = hv.y;
            ulonglong2 cv = cwp[j];  cw2[2*j] = cv.x; cw2[2*j+1] = cv.y;
            ulonglong2 av = ap[j];   a2[2*j] = av.x;  a2[2*j+1] = av.y;
        }
    }
    const float dv = Dv[d];

    cp_async_wait0();
    __syncthreads();

    const size_t ybase = base + dl;

#pragma unroll
    for (int l = 0; l < LC; l++) {
        ull accA = 0ull, accB = 0ull;
#pragma unroll
        for (int j = 0; j < 2; j++) {
            ulonglong2 bv = bts[l][sh * 2 + j];
            h2[2*j+0] = fma2(a2[2*j+0], h2[2*j+0], bv.x);
            h2[2*j+1] = fma2(a2[2*j+1], h2[2*j+1], bv.y);
            accA = fma2(cw2[2*j+0], h2[2*j+0], accA);
            accB = fma2(cw2[2*j+1], h2[2*j+1], accB);
        }
        float2 ua = unpack2(accA);
        float2 ub = unpack2(accB);
        float part = (ua.x + ua.y) + (ub.x + ub.y);
        part += __shfl_xor_sync(0xffffffffu, part, 1);
        if (sh == 0) {
            float xval = sx[l * 64 + dl];
            y[ybase + (size_t)l * DMODEL] = fmaf(dv, xval, part);
        }
    }
}

// ---------------------------------------------------------------------------
extern "C" void kernel_launch(void* const* d_in, const int* in_sizes, int n_in,
                              void* d_out, int out_size) {
    const float* x    = (const float*)d_in[0];   // (B, L, D)
    const float* logA = (const float*)d_in[1];   // (D, S)
    const float* Bw   = (const float*)d_in[2];   // (S, D)
    const float* Cw   = (const float*)d_in[3];   // (D, S)
    const float* Dv   = (const float*)d_in[4];   // (D,)
    float* y = (float*)d_out;                    // (B, L, D)

    // K1 (+ fused K0 precompute in trailing blocks); 4 rows per warp
    k1_bproj<<<K1_BLOCKS + K0_BLOCKS, 128>>>(x, Bw, logA);

    {
        dim3 grid(NC, DMODEL / 64, BATCH);
        k2_localscan<<<grid, 128>>>();
    }
    {
        dim3 grid(DMODEL * DSTATE / 64, BATCH);
        k3_combine<<<grid, 256>>>();
    }
    {
        dim3 grid(NC, DMODEL / 64, BATCH);
        k4_output<<<grid, 128>>>(x, Cw, Dv, y);
    }
}